// round 6
// baseline (speedup 1.0000x reference)
#include <cuda_runtime.h>
#include <cstdint>

// ---------------------------------------------------------------------------
// PatchMerging (B=64, H=W=28, DIM=384):
//   1) gather 2x2 quadrants -> 1536-vec, LayerNorm, round-to-tf32 -> g_mbuf
//   2) round w_reduction to tf32 (rne) -> g_wred
//   3) mma.sync tf32 GEMM (12544x1536) x (768x1536)^T -> rows 1..196
//      tile 256x128x32, 8 warps (4Mx2N), warp tile 64x64, 4-stage cp.async,
//      k16-grouped fragment layout => all LDS are 128-bit.
//   4) cls GEMM (64x384) x (768x384)^T -> row 0 (warp per output)
// ---------------------------------------------------------------------------

#define BATCH   64
#define LSEQ    785
#define DIM     384
#define FDIM    1536
#define ODIM    768
#define NPOS    196
#define MROWS   (BATCH * NPOS)   // 12544
#define OUTROWS 197

__device__ float g_mbuf[(size_t)MROWS * FDIM];
__device__ float g_wred[(size_t)ODIM * FDIM];

// ------------------------------ helpers -----------------------------------
__device__ __forceinline__ uint32_t smem_u32(const void* p) {
    uint32_t a;
    asm("{ .reg .u64 t; cvta.to.shared.u64 t, %1; cvt.u32.u64 %0, t; }"
        : "=r"(a) : "l"(p));
    return a;
}
__device__ __forceinline__ float tf32_rna(float x) {
    uint32_t r;
    asm("cvt.rna.tf32.f32 %0, %1;" : "=r"(r) : "f"(x));
    return __uint_as_float(r);
}
#define CP_ASYNC16(saddr, gptr) \
    asm volatile("cp.async.cg.shared.global [%0], [%1], 16;" :: "r"(saddr), "l"(gptr))
#define CP_COMMIT() asm volatile("cp.async.commit_group;" ::: "memory")
template <int N>
__device__ __forceinline__ void cp_wait() {
    asm volatile("cp.async.wait_group %0;" :: "n"(N) : "memory");
}

__device__ __forceinline__ void mma_tf32(float* d, uint32_t a0, uint32_t a1,
                                         uint32_t a2, uint32_t a3,
                                         uint32_t b0, uint32_t b1) {
    asm volatile(
        "mma.sync.aligned.m16n8k8.row.col.f32.tf32.tf32.f32 "
        "{%0,%1,%2,%3}, {%4,%5,%6,%7}, {%8,%9}, {%0,%1,%2,%3};"
        : "+f"(d[0]), "+f"(d[1]), "+f"(d[2]), "+f"(d[3])
        : "r"(a0), "r"(a1), "r"(a2), "r"(a3), "r"(b0), "r"(b1));
}

// ---------------------------------------------------------------------------
// Kernel 1: gather + LayerNorm (+ tf32 rne rounding on write)
// ---------------------------------------------------------------------------
__global__ __launch_bounds__(192) void ln_gather_kernel(
    const float* __restrict__ x,
    const float* __restrict__ gamma,
    const float* __restrict__ beta,
    float* __restrict__ mbuf)
{
    const int r   = blockIdx.x;
    const int b   = r / NPOS;
    const int n   = r - b * NPOS;
    const int h2  = n / 14;
    const int w2  = n - h2 * 14;
    const int tid = threadIdx.x;

    const float* xb = x + (size_t)b * LSEQ * DIM;
    const int rowbase = 1 + (2 * h2) * 28 + 2 * w2;

    float4 v[2];
    float s = 0.f, ss = 0.f;
#pragma unroll
    for (int i = 0; i < 2; i++) {
        const int f4 = tid + i * 192;
        const int f  = f4 * 4;
        const int q  = f / DIM;
        const int c  = f - q * DIM;
        const int drow = q & 1;
        const int dcol = q >> 1;
        const int L = rowbase + drow * 28 + dcol;
        const float4 val = *(const float4*)(xb + (size_t)L * DIM + c);
        v[i] = val;
        s  += val.x + val.y + val.z + val.w;
        ss += val.x * val.x + val.y * val.y + val.z * val.z + val.w * val.w;
    }

    __shared__ float red_s[6], red_ss[6];
#pragma unroll
    for (int off = 16; off > 0; off >>= 1) {
        s  += __shfl_xor_sync(0xFFFFFFFFu, s,  off);
        ss += __shfl_xor_sync(0xFFFFFFFFu, ss, off);
    }
    const int warp = tid >> 5;
    const int lane = tid & 31;
    if (lane == 0) { red_s[warp] = s; red_ss[warp] = ss; }
    __syncthreads();
    if (warp == 0) {
        float a = (lane < 6) ? red_s[lane]  : 0.f;
        float c = (lane < 6) ? red_ss[lane] : 0.f;
#pragma unroll
        for (int off = 4; off > 0; off >>= 1) {
            a += __shfl_xor_sync(0xFFFFFFFFu, a, off);
            c += __shfl_xor_sync(0xFFFFFFFFu, c, off);
        }
        if (lane == 0) { red_s[0] = a; red_ss[0] = c; }
    }
    __syncthreads();

    const float inv  = 1.0f / (float)FDIM;
    const float mean = red_s[0] * inv;
    const float var  = red_ss[0] * inv - mean * mean;
    const float rstd = rsqrtf(var + 1e-5f);

    float* mrow = mbuf + (size_t)r * FDIM;
#pragma unroll
    for (int i = 0; i < 2; i++) {
        const int f4 = tid + i * 192;
        const int f  = f4 * 4;
        const float4 g = *(const float4*)(gamma + f);
        const float4 be = *(const float4*)(beta + f);
        float4 o;
        o.x = tf32_rna((v[i].x - mean) * rstd * g.x + be.x);
        o.y = tf32_rna((v[i].y - mean) * rstd * g.y + be.y);
        o.z = tf32_rna((v[i].z - mean) * rstd * g.z + be.z);
        o.w = tf32_rna((v[i].w - mean) * rstd * g.w + be.w);
        *(float4*)(mrow + f) = o;
    }
}

// ---------------------------------------------------------------------------
// Kernel 1b: round w_reduction -> tf32 (rne)
// ---------------------------------------------------------------------------
__global__ __launch_bounds__(256) void wround_kernel(const float* __restrict__ w,
                                                     float* __restrict__ wo)
{
    const int i = blockIdx.x * 256 + threadIdx.x;
    wo[i] = tf32_rna(w[i]);
}

// ---------------------------------------------------------------------------
// Kernel 2: tf32 mma.sync GEMM, 256x128x32 tile, warp tile 64x64.
// k16 grouping: within a 16-wide k group, thread quarter c (=lane&3) owns
// k = 4c..4c+3 (one float4). mma step s in {0,1}:
//   slot c   <- k 4c+2s    slot c+4 <- k 4c+2s+1
// Applied identically to A and B (reduction order free), so every fragment
// load is a single LDS.128.
// ---------------------------------------------------------------------------
#define BM 256
#define BN 128
#define BK 32
#define ROWF 36
#define A_TILE_F (BM * ROWF)
#define B_TILE_F (BN * ROWF)
#define STAGE_F (A_TILE_F + B_TILE_F)
#define NSTAGE 4
#define NCHUNK (FDIM / BK)                   // 48
#define GEMM_SMEM (NSTAGE * STAGE_F * 4)     // 221184 bytes

__global__ __launch_bounds__(256) void gemm_mma_kernel(
    const float* __restrict__ A,
    const float* __restrict__ W,
    float* __restrict__ out)
{
    extern __shared__ __align__(16) float sm[];

    const int tid  = threadIdx.x;
    const int lane = tid & 31;
    const int wid  = tid >> 5;
    const int m0 = blockIdx.y * BM;
    const int n0 = blockIdx.x * BN;
    const int wm = (wid >> 1) * 64;
    const int wn = (wid & 1) * 64;

    const float* gA = A + (size_t)m0 * FDIM;
    const float* gB = W + (size_t)n0 * FDIM;

    const int lrow = tid >> 1;
    const int lseg = (tid & 1) * 4;
    const uint32_t smbase = smem_u32(sm);

    auto load_chunk = [&](int chunk, int stage) {
        const uint32_t base = smbase + (uint32_t)stage * (STAGE_F * 4);
        const int koff = chunk * BK;
        const float* pA0 = gA + (size_t)lrow * FDIM + koff;
        const float* pA1 = pA0 + (size_t)128 * FDIM;
        const uint32_t sA0 = base + (uint32_t)lrow * (ROWF * 4);
        const uint32_t sA1 = base + (uint32_t)(lrow + 128) * (ROWF * 4);
#pragma unroll
        for (int i = 0; i < 4; i++)
            CP_ASYNC16(sA0 + (lseg + i) * 16, pA0 + (lseg + i) * 4);
#pragma unroll
        for (int i = 0; i < 4; i++)
            CP_ASYNC16(sA1 + (lseg + i) * 16, pA1 + (lseg + i) * 4);
        const float* pB = gB + (size_t)lrow * FDIM + koff;
        const uint32_t sB = base + (A_TILE_F * 4) + (uint32_t)lrow * (ROWF * 4);
#pragma unroll
        for (int i = 0; i < 4; i++)
            CP_ASYNC16(sB + (lseg + i) * 16, pB + (lseg + i) * 4);
        CP_COMMIT();
    };

    float acc[4][8][4];
#pragma unroll
    for (int mt = 0; mt < 4; mt++)
#pragma unroll
        for (int nt = 0; nt < 8; nt++)
#pragma unroll
            for (int j = 0; j < 4; j++) acc[mt][nt][j] = 0.f;

    load_chunk(0, 0);
    load_chunk(1, 1);
    load_chunk(2, 2);
    cp_wait<2>();
    __syncthreads();

    const int g2 = lane >> 2;                // 0..7
    const int c4 = 4 * (lane & 3);           // 0,4,8,12 : float4 base within k16

    for (int i = 0; i < NCHUNK; i++) {
        const int ld = i + 3;
        if (ld < NCHUNK) load_chunk(ld, ld % NSTAGE);

        const int s = i % NSTAGE;
        const float* As = sm + s * STAGE_F;
        const float* Bs = As + A_TILE_F;

#pragma unroll
        for (int g = 0; g < 2; g++) {        // two k16 groups per chunk
            const int kb = g * 16 + c4;
            float4 aLo[4], aHi[4];
#pragma unroll
            for (int mt = 0; mt < 4; mt++) {
                const int r = wm + mt * 16 + g2;
                aLo[mt] = *(const float4*)(As + r * ROWF + kb);
                aHi[mt] = *(const float4*)(As + (r + 8) * ROWF + kb);
            }
            float4 bv[8];
#pragma unroll
            for (int nt = 0; nt < 8; nt++) {
                const int n = wn + nt * 8 + g2;
                bv[nt] = *(const float4*)(Bs + n * ROWF + kb);
            }
            // step 0: elements (x, y)
#pragma unroll
            for (int nt = 0; nt < 8; nt++)
#pragma unroll
                for (int mt = 0; mt < 4; mt++)
                    mma_tf32(acc[mt][nt],
                             __float_as_uint(aLo[mt].x), __float_as_uint(aHi[mt].x),
                             __float_as_uint(aLo[mt].y), __float_as_uint(aHi[mt].y),
                             __float_as_uint(bv[nt].x),  __float_as_uint(bv[nt].y));
            // step 1: elements (z, w)
#pragma unroll
            for (int nt = 0; nt < 8; nt++)
#pragma unroll
                for (int mt = 0; mt < 4; mt++)
                    mma_tf32(acc[mt][nt],
                             __float_as_uint(aLo[mt].z), __float_as_uint(aHi[mt].z),
                             __float_as_uint(aLo[mt].w), __float_as_uint(aHi[mt].w),
                             __float_as_uint(bv[nt].z),  __float_as_uint(bv[nt].w));
        }

        if (ld < NCHUNK) { cp_wait<2>(); } else { cp_wait<0>(); }
        __syncthreads();
    }

    // epilogue: write with batch/row remap
    const int c2 = 2 * (lane & 3);
#pragma unroll
    for (int mt = 0; mt < 4; mt++) {
        const int mA = m0 + wm + mt * 16 + g2;
#pragma unroll
        for (int half = 0; half < 2; half++) {
            const int m  = mA + half * 8;
            const int b  = m / NPOS;
            const int nn = m - b * NPOS;
            float* orow = out + ((size_t)b * OUTROWS + 1 + nn) * ODIM + n0 + wn;
#pragma unroll
            for (int nt = 0; nt < 8; nt++) {
                float2 v;
                v.x = acc[mt][nt][2 * half + 0];
                v.y = acc[mt][nt][2 * half + 1];
                *(float2*)(orow + nt * 8 + c2) = v;
            }
        }
    }
}

// ---------------------------------------------------------------------------
// Kernel 3: cls GEMM, warp per output element.
// ---------------------------------------------------------------------------
__global__ __launch_bounds__(256) void cls_kernel(
    const float* __restrict__ x,
    const float* __restrict__ wc,
    float* __restrict__ out)
{
    const int warp = threadIdx.x >> 5;
    const int lane = threadIdx.x & 31;
    const int idx  = blockIdx.x * 8 + warp;
    const int b    = idx / ODIM;
    const int o    = idx - b * ODIM;

    const float4* wrow = (const float4*)(wc + (size_t)o * DIM);
    const float4* xrow = (const float4*)(x + (size_t)b * LSEQ * DIM);

    float s = 0.f;
#pragma unroll
    for (int j = 0; j < 3; j++) {
        const float4 wv = wrow[lane + 32 * j];
        const float4 xv = xrow[lane + 32 * j];
        s += wv.x * xv.x + wv.y * xv.y + wv.z * xv.z + wv.w * xv.w;
    }
#pragma unroll
    for (int off = 16; off > 0; off >>= 1)
        s += __shfl_xor_sync(0xFFFFFFFFu, s, off);

    if (lane == 0)
        out[(size_t)b * OUTROWS * ODIM + o] = s;
}

// ---------------------------------------------------------------------------
extern "C" void kernel_launch(void* const* d_in, const int* in_sizes, int n_in,
                              void* d_out, int out_size)
{
    const float* x     = (const float*)d_in[0];
    const float* w_red = (const float*)d_in[1];
    const float* w_cvt = (const float*)d_in[2];
    const float* gamma = (const float*)d_in[3];
    const float* beta  = (const float*)d_in[4];
    float* out = (float*)d_out;

    float* mbuf;
    float* wred;
    cudaGetSymbolAddress((void**)&mbuf, g_mbuf);
    cudaGetSymbolAddress((void**)&wred, g_wred);

    cudaFuncSetAttribute(gemm_mma_kernel,
                         cudaFuncAttributeMaxDynamicSharedMemorySize, GEMM_SMEM);

    cls_kernel<<<(BATCH * ODIM) / 8, 256>>>(x, w_cvt, out);
    wround_kernel<<<(ODIM * FDIM) / 256, 256>>>(w_red, wred);
    ln_gather_kernel<<<MROWS, 192>>>(x, gamma, beta, mbuf);
    gemm_mma_kernel<<<dim3(ODIM / BN, MROWS / BM), 256, GEMM_SMEM>>>(mbuf, wred, out);
}